// round 15
// baseline (speedup 1.0000x reference)
#include <cuda_runtime.h>
#include <cuda_fp16.h>
#include <cstdint>
#include <cstddef>

#define BB 16
#define CC 256
#define HH 64
#define WW 64
#define NHEAD 8
#define HD 32
#define NPIX 4096

// Scratch (device globals; no allocations allowed)
__device__ __half g_qkv[(size_t)BB * 3 * CC * NPIX];   // fp16 qkv
__device__ float g_lambda[BB * NHEAD * HD * HD];
__device__ float g_lampart[BB * NHEAD * 8 * HD * HD];
__device__ float g_lamsum[BB * NHEAD * 8 * HD];

// fp16 operands (activations single-rounded; weights split hi/lo)
__device__ __half g_srcf[(size_t)BB * CC * NPIX];
__device__ __half g_resf[(size_t)BB * CC * NPIX];
__device__ __half g_wch[CC * CC * 9];
__device__ __half g_wcl[CC * CC * 9];
__device__ __half g_wqh[3 * CC * CC];
__device__ __half g_wql[3 * CC * CC];
__device__ __half g_woh[CC * CC];
__device__ __half g_wol[CC * CC];

// ---------------------------------------------------------------------------
__device__ __forceinline__ void half_split(float x, __half& hi, __half& lo) {
    hi = __float2half_rn(x);
    lo = __float2half_rn(x - __half2float(hi));
}
__device__ __forceinline__ uint32_t smem_to_u32(const void* p) {
    uint32_t a;
    asm("{ .reg .u64 t; cvta.to.shared.u64 t, %1; cvt.u32.u64 %0, t; }" : "=r"(a) : "l"(p));
    return a;
}
__device__ __forceinline__ void mma_f16(float* d, const uint32_t* a, const uint32_t* b) {
    asm volatile(
        "mma.sync.aligned.m16n8k16.row.col.f32.f16.f16.f32 "
        "{%0,%1,%2,%3}, {%4,%5,%6,%7}, {%8,%9}, {%0,%1,%2,%3};"
        : "+f"(d[0]), "+f"(d[1]), "+f"(d[2]), "+f"(d[3])
        : "r"(a[0]), "r"(a[1]), "r"(a[2]), "r"(a[3]), "r"(b[0]), "r"(b[1]));
}
#define LDSM4(R, ADDR) \
    asm volatile("ldmatrix.sync.aligned.m8n8.x4.shared.b16 {%0,%1,%2,%3}, [%4];" \
        : "=r"((R)[0]), "=r"((R)[1]), "=r"((R)[2]), "=r"((R)[3]) : "r"(ADDR))
#define LDSM4T(R, ADDR) \
    asm volatile("ldmatrix.sync.aligned.m8n8.x4.trans.shared.b16 {%0,%1,%2,%3}, [%4];" \
        : "=r"((R)[0]), "=r"((R)[1]), "=r"((R)[2]), "=r"((R)[3]) : "r"(ADDR))

// ---------------------------------------------------------------------------
// HMMA GEMM / implicit conv, fp16, 2-term weight split:
// D = (Ah+Al)·B  -> 2 MMAs per k16 chunk.
// Tiles M=128, N=128, Kslab=64; 8 warps 4(M)x2(N); double-buffered SMEM.
// ---------------------------------------------------------------------------
#define KS 64
#define ASTR 72
#define BSTR 136
#define A_ELEMS (128 * ASTR)
#define B_ELEMS (KS * BSTR)
#define ASZB (A_ELEMS * 2)
#define STAGE_ELEMS (2 * A_ELEMS + B_ELEMS)
#define STAGE_BYTES (STAGE_ELEMS * 2)
#define SMEM_BYTES (2 * STAGE_BYTES)

__global__ void __launch_bounds__(256, 2)
gemm_mma(const __half* __restrict__ Ah, const __half* __restrict__ Al,
         const __half* __restrict__ B,
         int nslabs, int O, int Ktot, int conv,
         float* __restrict__ outF, __half* __restrict__ outH,
         const float* __restrict__ bias, const float* __restrict__ residF)
{
    extern __shared__ __align__(16) __half smem[];

    const int tid  = threadIdx.x;
    const int warp = tid >> 5, lane = tid & 31;
    const int mw = warp & 3, nw = warp >> 2;
    const int g  = lane >> 2, t = lane & 3;
    const int grp = lane >> 3, r = lane & 7;
    const int n0 = blockIdx.x * 128;
    const int o0 = blockIdx.y * 128;
    const int b  = blockIdx.z;

    const uint32_t uS = smem_to_u32(smem);
    const int aoff = (((grp & 1) << 3) + r) * ASTR + ((grp >> 1) << 3);
    const int boff = (((grp & 1) << 3) + r) * BSTR + ((grp >> 1) << 3) + nw * 64;

    const __half* Bb = B + (size_t)b * 256 * NPIX;

    float acc[2][8][4];
    #pragma unroll
    for (int mt = 0; mt < 2; mt++)
        #pragma unroll
        for (int nt = 0; nt < 8; nt++)
            #pragma unroll
            for (int q = 0; q < 4; q++) acc[mt][nt][q] = 0.f;

    auto fill = [&](int s, int st) {
        __half* pA0 = smem + st * STAGE_ELEMS;
        __half* pA1 = pA0 + A_ELEMS;
        __half* pB0 = pA0 + 2 * A_ELEMS;
        const int k0 = s * KS;
        // A: 128 o x 64 k (hi + lo)
        #pragma unroll
        for (int it = 0; it < 4; it++) {
            int idx = tid + it * 256;
            int q = idx & 7, o = idx >> 3;
            size_t goff = (size_t)(o0 + o) * Ktot + k0 + q * 8;
            *(uint4*)&pA0[o * ASTR + q * 8] = *(const uint4*)(Ah + goff);
            *(uint4*)&pA1[o * ASTR + q * 8] = *(const uint4*)(Al + goff);
        }
        // B: 64 k x 128 n
        if (!conv) {
            #pragma unroll
            for (int it = 0; it < 4; it++) {
                int idx = tid + it * 256;
                int a = idx & 15, k = idx >> 4;
                size_t goff = (size_t)(k0 + k) * NPIX + n0 + a * 8;
                *(uint4*)&pB0[k * BSTR + a * 8] = *(const uint4*)(Bb + goff);
            }
        } else {
            const int tap = s >> 2, c0 = (s & 3) * KS;
            const int dh = tap / 3 - 1, dw = tap % 3 - 1;
            #pragma unroll
            for (int it = 0; it < 4; it++) {
                int idx = tid + it * 256;
                int a = idx & 15, k = idx >> 4;
                int pixb = n0 + a * 8;
                int h = pixb >> 6, w0 = pixb & 63;
                int hs = h + dh;
                bool okh = (unsigned)hs < 64u;
                const __half* rowp = Bb + (size_t)(c0 + k) * NPIX + hs * 64;
                uint4 v = make_uint4(0, 0, 0, 0);
                if (okh) v = *(const uint4*)(rowp + w0);
                uint4 o4;
                if (dw == 0) {
                    o4 = v;
                } else if (dw == 1) {
                    uint32_t ex = (okh && w0 + 8 < 64)
                        ? (uint32_t)*(const unsigned short*)(rowp + w0 + 8) : 0u;
                    o4.x = (v.x >> 16) | (v.y << 16);
                    o4.y = (v.y >> 16) | (v.z << 16);
                    o4.z = (v.z >> 16) | (v.w << 16);
                    o4.w = (v.w >> 16) | (ex << 16);
                } else {
                    uint32_t ex = (okh && w0 > 0)
                        ? (uint32_t)*(const unsigned short*)(rowp + w0 - 1) : 0u;
                    o4.x = (v.x << 16) | ex;
                    o4.y = (v.y << 16) | (v.x >> 16);
                    o4.z = (v.z << 16) | (v.y >> 16);
                    o4.w = (v.w << 16) | (v.z >> 16);
                }
                *(uint4*)&pB0[k * BSTR + a * 8] = o4;
            }
        }
    };

    fill(0, 0);
    __syncthreads();

    for (int s = 0; s < nslabs; s++) {
        const int cur = s & 1;
        if (s + 1 < nslabs) fill(s + 1, cur ^ 1);

        const uint32_t uAst = uS + cur * STAGE_BYTES;
        const uint32_t uBst = uAst + 2 * ASZB;
        #pragma unroll
        for (int kt = 0; kt < 4; kt++) {
            uint32_t ah[2][4], al[2][4];
            #pragma unroll
            for (int mt = 0; mt < 2; mt++) {
                uint32_t ad = uAst + 2 * (aoff + (mw * 32 + mt * 16) * ASTR + kt * 16);
                LDSM4(ah[mt], ad);
                LDSM4(al[mt], ad + ASZB);
            }
            #pragma unroll
            for (int ntp = 0; ntp < 4; ntp++) {
                uint32_t bd = uBst + 2 * (boff + ntp * 16 + kt * 16 * BSTR);
                uint32_t bh[4];
                LDSM4T(bh, bd);
                #pragma unroll
                for (int mt = 0; mt < 2; mt++) {
                    mma_f16(acc[mt][ntp * 2],     ah[mt], &bh[0]);
                    mma_f16(acc[mt][ntp * 2 + 1], ah[mt], &bh[2]);
                    mma_f16(acc[mt][ntp * 2],     al[mt], &bh[0]);
                    mma_f16(acc[mt][ntp * 2 + 1], al[mt], &bh[2]);
                }
            }
        }
        __syncthreads();
    }

    // ---- epilogue
    #pragma unroll
    for (int mt = 0; mt < 2; mt++) {
        int o_lo = o0 + mw * 32 + mt * 16 + g;
        int o_hi = o_lo + 8;
        float b_lo = bias ? bias[o_lo] : 0.f;
        float b_hi = bias ? bias[o_hi] : 0.f;
        #pragma unroll
        for (int nt = 0; nt < 8; nt++) {
            int n = n0 + nw * 64 + nt * 8 + t * 2;
            size_t off_lo = ((size_t)b * O + o_lo) * NPIX + n;
            size_t off_hi = ((size_t)b * O + o_hi) * NPIX + n;
            float2 v0 = make_float2(acc[mt][nt][0] + b_lo, acc[mt][nt][1] + b_lo);
            float2 v1 = make_float2(acc[mt][nt][2] + b_hi, acc[mt][nt][3] + b_hi);
            if (residF) {
                float2 r0 = *(const float2*)(residF + off_lo);
                float2 r1 = *(const float2*)(residF + off_hi);
                v0.x += r0.x; v0.y += r0.y;
                v1.x += r1.x; v1.y += r1.y;
            }
            if (outF) {
                *(float2*)(outF + off_lo) = v0;
                *(float2*)(outF + off_hi) = v1;
            } else {
                *(__half2*)(outH + off_lo) = __floats2half2_rn(v0.x, v0.y);
                *(__half2*)(outH + off_hi) = __floats2half2_rn(v1.x, v1.y);
            }
        }
    }
}

// ---------------------------------------------------------------------------
// Prep kernels
// ---------------------------------------------------------------------------
__global__ void split_pass(const float* __restrict__ in, __half* __restrict__ hi,
                           __half* __restrict__ lo, int n4)
{
    int idx = blockIdx.x * blockDim.x + threadIdx.x;
    if (idx >= n4) return;
    float4 v = ((const float4*)in)[idx];
    __half h[4], l[4];
    half_split(v.x, h[0], l[0]);
    half_split(v.y, h[1], l[1]);
    half_split(v.z, h[2], l[2]);
    half_split(v.w, h[3], l[3]);
    *(uint2*)(hi + (size_t)idx * 4) = *(uint2*)h;
    *(uint2*)(lo + (size_t)idx * 4) = *(uint2*)l;
}

__global__ void round_pass(const float* __restrict__ in, __half* __restrict__ out, int n4)
{
    int idx = blockIdx.x * blockDim.x + threadIdx.x;
    if (idx >= n4) return;
    float4 v = ((const float4*)in)[idx];
    __half h[4];
    h[0] = __float2half_rn(v.x);
    h[1] = __float2half_rn(v.y);
    h[2] = __float2half_rn(v.z);
    h[3] = __float2half_rn(v.w);
    *(uint2*)(out + (size_t)idx * 4) = *(uint2*)h;
}

__global__ void wtc_kernel(const float* __restrict__ cpe_w,
                           __half* __restrict__ wh, __half* __restrict__ wl)
{
    int o = blockIdx.x, c = threadIdx.x;
    #pragma unroll
    for (int tp = 0; tp < 9; tp++) {
        float v = cpe_w[((size_t)o * 256 + c) * 9 + tp];
        __half h, l;
        half_split(v, h, l);
        wh[(size_t)o * 2304 + tp * 256 + c] = h;
        wl[(size_t)o * 2304 + tp * 256 + c] = l;
    }
}

// ---------------------------------------------------------------------------
// content_lambda partials, no-max softmax: P_c = sum exp(k)·v ; s_c = sum exp(k)
// (|k| <~ 8 for this problem's input distribution -> exp(k) safely in fp32)
// grid (8 chunks, 128 bp); each chunk covers 512 n.
// ---------------------------------------------------------------------------
__global__ __launch_bounds__(256) void lambda_partial_kernel(float* __restrict__ part,
                                                             float* __restrict__ psum)
{
    const int chunk = blockIdx.x;
    const int bp = blockIdx.y;
    const int b = bp >> 3, head = bp & 7;
    const __half* kbase = g_qkv + ((size_t)b * 3 * CC + CC + head * HD) * NPIX;
    const __half* vbase = g_qkv + ((size_t)b * 3 * CC + 2 * CC + head * HD) * NPIX;

    __shared__ float kf[32][129];
    __shared__ float vv[32][129];
    __shared__ float srow[32];

    const int tid = threadIdx.x;
    if (tid < 32) srow[tid] = 0.f;
    __syncthreads();

    const int o = tid & 31;
    const int ib = (tid >> 5) * 4;
    float acc[4] = {};

    const int nbeg = chunk * 512, nend = nbeg + 512;
    for (int n0 = nbeg; n0 < nend; n0 += 128) {
        for (int idx = tid; idx < 32 * 128; idx += 256) {
            int rr = idx >> 7, n = idx & 127;
            float e = __expf(__half2float(kbase[(size_t)rr * NPIX + n0 + n]));
            kf[rr][n] = e;
            vv[rr][n] = __half2float(vbase[(size_t)rr * NPIX + n0 + n]);
            // warp covers 32 consecutive idx -> same row rr; reduce then one atomic
            #pragma unroll
            for (int off = 16; off > 0; off >>= 1)
                e += __shfl_xor_sync(0xFFFFFFFFu, e, off);
            if ((tid & 31) == 0) atomicAdd(&srow[rr], e);
        }
        __syncthreads();
        #pragma unroll 4
        for (int n = 0; n < 128; n++) {
            float vval = vv[o][n];
            #pragma unroll
            for (int j = 0; j < 4; j++) acc[j] += kf[ib + j][n] * vval;
        }
        __syncthreads();
    }
    #pragma unroll
    for (int j = 0; j < 4; j++)
        part[((size_t)bp * 8 + chunk) * 1024 + (ib + j) * 32 + o] = acc[j];
    if (tid < 32) psum[((size_t)bp * 8 + chunk) * 32 + tid] = srow[tid];
}

__global__ __launch_bounds__(256) void lambda_reduce_kernel(const float* __restrict__ part,
                                                            const float* __restrict__ psum,
                                                            float* __restrict__ lam)
{
    const int bp = blockIdx.x;
    __shared__ float sinv[32];
    const int tid = threadIdx.x;
    if (tid < 32) {
        float s = 0.f;
        #pragma unroll
        for (int c = 0; c < 8; c++) s += psum[((size_t)bp * 8 + c) * 32 + tid];
        sinv[tid] = 1.f / s;
    }
    __syncthreads();
    for (int idx = tid; idx < 1024; idx += 256) {
        float s = 0.f;
        #pragma unroll
        for (int c = 0; c < 8; c++) s += part[((size_t)bp * 8 + c) * 1024 + idx];
        lam[(size_t)bp * 1024 + idx] = s * sinv[idx >> 5];
    }
}

// ---------------------------------------------------------------------------
// Fused content + depthwise 5x5 pos-lambda + combine (q, v fp16 in; fp16 out)
// ---------------------------------------------------------------------------
__global__ __launch_bounds__(256) void fused_kernel(const float* __restrict__ lam,
                                                    const float* __restrict__ rel,
                                                    __half* __restrict__ resf)
{
    const int h0 = blockIdx.x * 4;
    const int o0 = blockIdx.y * 16;
    const int bp = blockIdx.z;
    const int b = bp >> 3, head = bp & 7;

    const __half* qbase = g_qkv + ((size_t)b * 3 * CC + head * HD) * NPIX;
    const __half* vbase = g_qkv + ((size_t)b * 3 * CC + 2 * CC + head * HD) * NPIX;

    __shared__ float lam_s[32][17];
    __shared__ float rel_s[16][25];
    __shared__ float v_s[16][8][68];

    const int tid = threadIdx.x;
    const float scale = 0.1767766953f;

    for (int idx = tid; idx < 32 * 16; idx += 256) {
        int i = idx >> 4, oo = idx & 15;
        lam_s[i][oo] = lam[(size_t)bp * 1024 + i * 32 + o0 + oo] * scale;
    }
    for (int idx = tid; idx < 16 * 25; idx += 256)
        rel_s[idx / 25][idx % 25] = rel[(o0 + idx / 25) * 25 + idx % 25];
    for (int idx = tid; idx < 16 * 8 * 68; idx += 256) {
        int o = idx / 544;
        int rem = idx % 544;
        int rr = rem / 68, c = rem % 68;
        int h = h0 - 2 + rr, w = c - 2;
        float val = 0.f;
        if (h >= 0 && h < HH && w >= 0 && w < WW)
            val = __half2float(vbase[(size_t)(o0 + o) * NPIX + h * WW + w]);
        v_s[o][rr][c] = val;
    }
    __syncthreads();

    const int wr = tid >> 6;
    const int w = tid & 63;
    const int n = (h0 + wr) * WW + w;

    float qreg[32];
    #pragma unroll
    for (int i = 0; i < 32; i++) qreg[i] = __half2float(qbase[(size_t)i * NPIX + n]);

    const size_t obase = ((size_t)b * CC + head * HD + o0) * NPIX + n;

    #pragma unroll 2
    for (int oo = 0; oo < 16; oo++) {
        float content = 0.f;
        #pragma unroll
        for (int i = 0; i < 32; i++) content += qreg[i] * lam_s[i][oo];
        float pos = 0.f;
        #pragma unroll
        for (int dh = 0; dh < 5; dh++)
            #pragma unroll
            for (int dw = 0; dw < 5; dw++)
                pos += rel_s[oo][dh * 5 + dw] * v_s[oo][wr + dh][w + dw];
        float val = content + qreg[o0 + oo] * pos;
        resf[obase + (size_t)oo * NPIX] = __float2half_rn(val);
    }
}

// ---------------------------------------------------------------------------
extern "C" void kernel_launch(void* const* d_in, const int* in_sizes, int n_in,
                              void* d_out, int out_size)
{
    const float* src   = (const float*)d_in[0];
    const float* rel   = (const float*)d_in[1];
    const float* qkv_w = (const float*)d_in[2];
    const float* cpe_w = (const float*)d_in[3];
    const float* cpe_b = (const float*)d_in[4];
    const float* out_w = (const float*)d_in[5];
    const float* out_b = (const float*)d_in[6];
    float* out = (float*)d_out;

    float *plam, *ppart, *ppsum;
    __half *pqkv, *psrcf, *presf;
    __half *pwch, *pwcl, *pwqh, *pwql, *pwoh, *pwol;
    cudaGetSymbolAddress((void**)&pqkv,  g_qkv);
    cudaGetSymbolAddress((void**)&plam,  g_lambda);
    cudaGetSymbolAddress((void**)&ppart, g_lampart);
    cudaGetSymbolAddress((void**)&ppsum, g_lamsum);
    cudaGetSymbolAddress((void**)&psrcf, g_srcf);
    cudaGetSymbolAddress((void**)&presf, g_resf);
    cudaGetSymbolAddress((void**)&pwch,  g_wch);
    cudaGetSymbolAddress((void**)&pwcl,  g_wcl);
    cudaGetSymbolAddress((void**)&pwqh,  g_wqh);
    cudaGetSymbolAddress((void**)&pwql,  g_wql);
    cudaGetSymbolAddress((void**)&pwoh,  g_woh);
    cudaGetSymbolAddress((void**)&pwol,  g_wol);

    cudaFuncSetAttribute(gemm_mma, cudaFuncAttributeMaxDynamicSharedMemorySize, SMEM_BYTES);

    // 0) operand prep
    round_pass<<<16384, 256>>>(src, psrcf, BB * CC * NPIX / 4);
    wtc_kernel<<<256, 256>>>(cpe_w, pwch, pwcl);
    split_pass<<<192, 256>>>(qkv_w, pwqh, pwql, 3 * CC * CC / 4);
    split_pass<<<64, 256>>>(out_w, pwoh, pwol, CC * CC / 4);

    // 1) CPE conv (implicit GEMM K=2304, 36 slabs) + bias + residual -> x (fp16)
    gemm_mma<<<dim3(32, 2, 16), 256, SMEM_BYTES>>>(pwch, pwcl, psrcf, 36, CC, 2304, 1,
                                                   nullptr, presf, cpe_b, src);
    // 2) qkv = qkv_w @ x -> fp16
    gemm_mma<<<dim3(32, 6, 16), 256, SMEM_BYTES>>>(pwqh, pwql, presf, 4, 3 * CC, CC, 0,
                                                   nullptr, pqkv, nullptr, nullptr);
    // 3) content lambda: unnormalized partials + per-row exp-sums, then reduce
    lambda_partial_kernel<<<dim3(8, 128), 256>>>(ppart, ppsum);
    lambda_reduce_kernel<<<128, 256>>>(ppart, ppsum, plam);
    // 4) fused content + pos-lambda -> result (fp16, overwrites x which is dead)
    fused_kernel<<<dim3(16, 2, 128), 256>>>(plam, rel, presf);
    // 5) output projection -> d_out fp32
    gemm_mma<<<dim3(32, 2, 16), 256, SMEM_BYTES>>>(pwoh, pwol, presf, 4, CC, CC, 0,
                                                   out, nullptr, out_b, nullptr);
}

// round 16
// speedup vs baseline: 1.5779x; 1.5779x over previous
#include <cuda_runtime.h>
#include <cuda_fp16.h>
#include <cstdint>
#include <cstddef>

#define BB 16
#define CC 256
#define HH 64
#define WW 64
#define NHEAD 8
#define HD 32
#define NPIX 4096

// Scratch (device globals; no allocations allowed)
__device__ __half g_qkv[(size_t)BB * 3 * CC * NPIX];   // fp16 qkv
__device__ float g_stats[BB * NHEAD * HD * 2];
__device__ float g_lambda[BB * NHEAD * HD * HD];
__device__ float g_lampart[BB * NHEAD * 8 * HD * HD];

// fp16 operands (activations single-rounded; weights split hi/lo)
__device__ __half g_srcf[(size_t)BB * CC * NPIX];
__device__ __half g_resf[(size_t)BB * CC * NPIX];
__device__ __half g_wch[CC * CC * 9];
__device__ __half g_wcl[CC * CC * 9];
__device__ __half g_wqh[3 * CC * CC];
__device__ __half g_wql[3 * CC * CC];
__device__ __half g_woh[CC * CC];
__device__ __half g_wol[CC * CC];

// ---------------------------------------------------------------------------
__device__ __forceinline__ void half_split(float x, __half& hi, __half& lo) {
    hi = __float2half_rn(x);
    lo = __float2half_rn(x - __half2float(hi));
}
__device__ __forceinline__ uint32_t smem_to_u32(const void* p) {
    uint32_t a;
    asm("{ .reg .u64 t; cvta.to.shared.u64 t, %1; cvt.u32.u64 %0, t; }" : "=r"(a) : "l"(p));
    return a;
}
__device__ __forceinline__ void mma_f16(float* d, const uint32_t* a, const uint32_t* b) {
    asm volatile(
        "mma.sync.aligned.m16n8k16.row.col.f32.f16.f16.f32 "
        "{%0,%1,%2,%3}, {%4,%5,%6,%7}, {%8,%9}, {%0,%1,%2,%3};"
        : "+f"(d[0]), "+f"(d[1]), "+f"(d[2]), "+f"(d[3])
        : "r"(a[0]), "r"(a[1]), "r"(a[2]), "r"(a[3]), "r"(b[0]), "r"(b[1]));
}
#define LDSM4(R, ADDR) \
    asm volatile("ldmatrix.sync.aligned.m8n8.x4.shared.b16 {%0,%1,%2,%3}, [%4];" \
        : "=r"((R)[0]), "=r"((R)[1]), "=r"((R)[2]), "=r"((R)[3]) : "r"(ADDR))
#define LDSM4T(R, ADDR) \
    asm volatile("ldmatrix.sync.aligned.m8n8.x4.trans.shared.b16 {%0,%1,%2,%3}, [%4];" \
        : "=r"((R)[0]), "=r"((R)[1]), "=r"((R)[2]), "=r"((R)[3]) : "r"(ADDR))

// ---------------------------------------------------------------------------
// HMMA GEMM / implicit conv, fp16, 2-term weight split:
// D = (Ah+Al)·B  -> 2 MMAs per k16 chunk.
// Tiles M=128, N=128, Kslab=64; 8 warps 4(M)x2(N); double-buffered SMEM.
// ---------------------------------------------------------------------------
#define KS 64
#define ASTR 72
#define BSTR 136
#define A_ELEMS (128 * ASTR)
#define B_ELEMS (KS * BSTR)
#define ASZB (A_ELEMS * 2)
#define STAGE_ELEMS (2 * A_ELEMS + B_ELEMS)
#define STAGE_BYTES (STAGE_ELEMS * 2)
#define SMEM_BYTES (2 * STAGE_BYTES)

__global__ void __launch_bounds__(256, 2)
gemm_mma(const __half* __restrict__ Ah, const __half* __restrict__ Al,
         const __half* __restrict__ B,
         int nslabs, int O, int Ktot, int conv,
         float* __restrict__ outF, __half* __restrict__ outH,
         const float* __restrict__ bias, const float* __restrict__ residF)
{
    extern __shared__ __align__(16) __half smem[];

    const int tid  = threadIdx.x;
    const int warp = tid >> 5, lane = tid & 31;
    const int mw = warp & 3, nw = warp >> 2;
    const int g  = lane >> 2, t = lane & 3;
    const int grp = lane >> 3, r = lane & 7;
    const int n0 = blockIdx.x * 128;
    const int o0 = blockIdx.y * 128;
    const int b  = blockIdx.z;

    const uint32_t uS = smem_to_u32(smem);
    const int aoff = (((grp & 1) << 3) + r) * ASTR + ((grp >> 1) << 3);
    const int boff = (((grp & 1) << 3) + r) * BSTR + ((grp >> 1) << 3) + nw * 64;

    const __half* Bb = B + (size_t)b * 256 * NPIX;

    float acc[2][8][4];
    #pragma unroll
    for (int mt = 0; mt < 2; mt++)
        #pragma unroll
        for (int nt = 0; nt < 8; nt++)
            #pragma unroll
            for (int q = 0; q < 4; q++) acc[mt][nt][q] = 0.f;

    auto fill = [&](int s, int st) {
        __half* pA0 = smem + st * STAGE_ELEMS;
        __half* pA1 = pA0 + A_ELEMS;
        __half* pB0 = pA0 + 2 * A_ELEMS;
        const int k0 = s * KS;
        // A: 128 o x 64 k (hi + lo)
        #pragma unroll
        for (int it = 0; it < 4; it++) {
            int idx = tid + it * 256;
            int q = idx & 7, o = idx >> 3;
            size_t goff = (size_t)(o0 + o) * Ktot + k0 + q * 8;
            *(uint4*)&pA0[o * ASTR + q * 8] = *(const uint4*)(Ah + goff);
            *(uint4*)&pA1[o * ASTR + q * 8] = *(const uint4*)(Al + goff);
        }
        // B: 64 k x 128 n
        if (!conv) {
            #pragma unroll
            for (int it = 0; it < 4; it++) {
                int idx = tid + it * 256;
                int a = idx & 15, k = idx >> 4;
                size_t goff = (size_t)(k0 + k) * NPIX + n0 + a * 8;
                *(uint4*)&pB0[k * BSTR + a * 8] = *(const uint4*)(Bb + goff);
            }
        } else {
            const int tap = s >> 2, c0 = (s & 3) * KS;
            const int dh = tap / 3 - 1, dw = tap % 3 - 1;
            #pragma unroll
            for (int it = 0; it < 4; it++) {
                int idx = tid + it * 256;
                int a = idx & 15, k = idx >> 4;
                int pixb = n0 + a * 8;
                int h = pixb >> 6, w0 = pixb & 63;
                int hs = h + dh;
                bool okh = (unsigned)hs < 64u;
                const __half* rowp = Bb + (size_t)(c0 + k) * NPIX + hs * 64;
                uint4 v = make_uint4(0, 0, 0, 0);
                if (okh) v = *(const uint4*)(rowp + w0);
                uint4 o4;
                if (dw == 0) {
                    o4 = v;
                } else if (dw == 1) {
                    uint32_t ex = (okh && w0 + 8 < 64)
                        ? (uint32_t)*(const unsigned short*)(rowp + w0 + 8) : 0u;
                    o4.x = (v.x >> 16) | (v.y << 16);
                    o4.y = (v.y >> 16) | (v.z << 16);
                    o4.z = (v.z >> 16) | (v.w << 16);
                    o4.w = (v.w >> 16) | (ex << 16);
                } else {
                    uint32_t ex = (okh && w0 > 0)
                        ? (uint32_t)*(const unsigned short*)(rowp + w0 - 1) : 0u;
                    o4.x = (v.x << 16) | ex;
                    o4.y = (v.y << 16) | (v.x >> 16);
                    o4.z = (v.z << 16) | (v.y >> 16);
                    o4.w = (v.w << 16) | (v.z >> 16);
                }
                *(uint4*)&pB0[k * BSTR + a * 8] = o4;
            }
        }
    };

    fill(0, 0);
    __syncthreads();

    for (int s = 0; s < nslabs; s++) {
        const int cur = s & 1;
        if (s + 1 < nslabs) fill(s + 1, cur ^ 1);

        const uint32_t uAst = uS + cur * STAGE_BYTES;
        const uint32_t uBst = uAst + 2 * ASZB;
        #pragma unroll
        for (int kt = 0; kt < 4; kt++) {
            uint32_t ah[2][4], al[2][4];
            #pragma unroll
            for (int mt = 0; mt < 2; mt++) {
                uint32_t ad = uAst + 2 * (aoff + (mw * 32 + mt * 16) * ASTR + kt * 16);
                LDSM4(ah[mt], ad);
                LDSM4(al[mt], ad + ASZB);
            }
            #pragma unroll
            for (int ntp = 0; ntp < 4; ntp++) {
                uint32_t bd = uBst + 2 * (boff + ntp * 16 + kt * 16 * BSTR);
                uint32_t bh[4];
                LDSM4T(bh, bd);
                #pragma unroll
                for (int mt = 0; mt < 2; mt++) {
                    mma_f16(acc[mt][ntp * 2],     ah[mt], &bh[0]);
                    mma_f16(acc[mt][ntp * 2 + 1], ah[mt], &bh[2]);
                    mma_f16(acc[mt][ntp * 2],     al[mt], &bh[0]);
                    mma_f16(acc[mt][ntp * 2 + 1], al[mt], &bh[2]);
                }
            }
        }
        __syncthreads();
    }

    // ---- epilogue
    #pragma unroll
    for (int mt = 0; mt < 2; mt++) {
        int o_lo = o0 + mw * 32 + mt * 16 + g;
        int o_hi = o_lo + 8;
        float b_lo = bias ? bias[o_lo] : 0.f;
        float b_hi = bias ? bias[o_hi] : 0.f;
        #pragma unroll
        for (int nt = 0; nt < 8; nt++) {
            int n = n0 + nw * 64 + nt * 8 + t * 2;
            size_t off_lo = ((size_t)b * O + o_lo) * NPIX + n;
            size_t off_hi = ((size_t)b * O + o_hi) * NPIX + n;
            float2 v0 = make_float2(acc[mt][nt][0] + b_lo, acc[mt][nt][1] + b_lo);
            float2 v1 = make_float2(acc[mt][nt][2] + b_hi, acc[mt][nt][3] + b_hi);
            if (residF) {
                float2 r0 = *(const float2*)(residF + off_lo);
                float2 r1 = *(const float2*)(residF + off_hi);
                v0.x += r0.x; v0.y += r0.y;
                v1.x += r1.x; v1.y += r1.y;
            }
            if (outF) {
                *(float2*)(outF + off_lo) = v0;
                *(float2*)(outF + off_hi) = v1;
            } else {
                *(__half2*)(outH + off_lo) = __floats2half2_rn(v0.x, v0.y);
                *(__half2*)(outH + off_hi) = __floats2half2_rn(v1.x, v1.y);
            }
        }
    }
}

// ---------------------------------------------------------------------------
// Prep kernels
// ---------------------------------------------------------------------------
__global__ void split_pass(const float* __restrict__ in, __half* __restrict__ hi,
                           __half* __restrict__ lo, int n4)
{
    int idx = blockIdx.x * blockDim.x + threadIdx.x;
    if (idx >= n4) return;
    float4 v = ((const float4*)in)[idx];
    __half h[4], l[4];
    half_split(v.x, h[0], l[0]);
    half_split(v.y, h[1], l[1]);
    half_split(v.z, h[2], l[2]);
    half_split(v.w, h[3], l[3]);
    *(uint2*)(hi + (size_t)idx * 4) = *(uint2*)h;
    *(uint2*)(lo + (size_t)idx * 4) = *(uint2*)l;
}

__global__ void round_pass(const float* __restrict__ in, __half* __restrict__ out, int n4)
{
    int idx = blockIdx.x * blockDim.x + threadIdx.x;
    if (idx >= n4) return;
    float4 v = ((const float4*)in)[idx];
    __half h[4];
    h[0] = __float2half_rn(v.x);
    h[1] = __float2half_rn(v.y);
    h[2] = __float2half_rn(v.z);
    h[3] = __float2half_rn(v.w);
    *(uint2*)(out + (size_t)idx * 4) = *(uint2*)h;
}

__global__ void wtc_kernel(const float* __restrict__ cpe_w,
                           __half* __restrict__ wh, __half* __restrict__ wl)
{
    int o = blockIdx.x, c = threadIdx.x;
    #pragma unroll
    for (int tp = 0; tp < 9; tp++) {
        float v = cpe_w[((size_t)o * 256 + c) * 9 + tp];
        __half h, l;
        half_split(v, h, l);
        wh[(size_t)o * 2304 + tp * 256 + c] = h;
        wl[(size_t)o * 2304 + tp * 256 + c] = l;
    }
}

// ---------------------------------------------------------------------------
// Softmax row stats (k is fp16, half2 loads)
// ---------------------------------------------------------------------------
__global__ __launch_bounds__(256) void softmax_stats_kernel(float* __restrict__ stats)
{
    const int row = blockIdx.x;
    const int bp = row >> 5, i = row & 31;
    const int b = bp >> 3, head = bp & 7;
    const __half2* k2 = (const __half2*)(g_qkv +
        ((size_t)b * 3 * CC + CC + head * HD + i) * NPIX);

    __shared__ float red[256];
    const int t = threadIdx.x;

    float m = -1e30f;
    #pragma unroll 4
    for (int n = t; n < NPIX / 2; n += 256) {
        float2 v = __half22float2(k2[n]);
        m = fmaxf(m, fmaxf(v.x, v.y));
    }
    red[t] = m; __syncthreads();
    for (int s = 128; s > 0; s >>= 1) { if (t < s) red[t] = fmaxf(red[t], red[t + s]); __syncthreads(); }
    m = red[0];
    __syncthreads();

    float sum = 0.f;
    #pragma unroll 4
    for (int n = t; n < NPIX / 2; n += 256) {
        float2 v = __half22float2(k2[n]);
        sum += __expf(v.x - m) + __expf(v.y - m);
    }
    red[t] = sum; __syncthreads();
    for (int s = 128; s > 0; s >>= 1) { if (t < s) red[t] += red[t + s]; __syncthreads(); }
    if (t == 0) { stats[row * 2] = m; stats[row * 2 + 1] = red[0]; }
}

// ---------------------------------------------------------------------------
// content_lambda partials + reduce (k, v fp16)
// ---------------------------------------------------------------------------
__global__ __launch_bounds__(256) void lambda_partial_kernel(const float* __restrict__ stats,
                                                             float* __restrict__ part)
{
    const int chunk = blockIdx.x;
    const int bp = blockIdx.y;
    const int b = bp >> 3, head = bp & 7;
    const __half* kbase = g_qkv + ((size_t)b * 3 * CC + CC + head * HD) * NPIX;
    const __half* vbase = g_qkv + ((size_t)b * 3 * CC + 2 * CC + head * HD) * NPIX;

    __shared__ float kf[32][129];
    __shared__ float vv[32][129];
    __shared__ float mi[32], si[32];

    const int tid = threadIdx.x;
    if (tid < 32) {
        mi[tid] = stats[(bp * 32 + tid) * 2];
        si[tid] = 1.f / stats[(bp * 32 + tid) * 2 + 1];
    }
    __syncthreads();

    const int o = tid & 31;
    const int ib = (tid >> 5) * 4;
    float acc[4] = {};

    const int nbeg = chunk * 512, nend = nbeg + 512;
    for (int n0 = nbeg; n0 < nend; n0 += 128) {
        for (int idx = tid; idx < 32 * 128; idx += 256) {
            int rr = idx >> 7, n = idx & 127;
            kf[rr][n] = __expf(__half2float(kbase[(size_t)rr * NPIX + n0 + n]) - mi[rr]) * si[rr];
            vv[rr][n] = __half2float(vbase[(size_t)rr * NPIX + n0 + n]);
        }
        __syncthreads();
        #pragma unroll 4
        for (int n = 0; n < 128; n++) {
            float vval = vv[o][n];
            #pragma unroll
            for (int j = 0; j < 4; j++) acc[j] += kf[ib + j][n] * vval;
        }
        __syncthreads();
    }
    #pragma unroll
    for (int j = 0; j < 4; j++)
        part[((size_t)bp * 8 + chunk) * 1024 + (ib + j) * 32 + o] = acc[j];
}

__global__ __launch_bounds__(256) void lambda_reduce_kernel(const float* __restrict__ part,
                                                            float* __restrict__ lam)
{
    const int bp = blockIdx.x;
    for (int idx = threadIdx.x; idx < 1024; idx += 256) {
        float s = 0.f;
        #pragma unroll
        for (int c = 0; c < 8; c++) s += part[((size_t)bp * 8 + c) * 1024 + idx];
        lam[(size_t)bp * 1024 + idx] = s;
    }
}

// ---------------------------------------------------------------------------
// Fused content + depthwise 5x5 pos-lambda + combine (q, v fp16 in; fp16 out)
// ---------------------------------------------------------------------------
__global__ __launch_bounds__(256) void fused_kernel(const float* __restrict__ lam,
                                                    const float* __restrict__ rel,
                                                    __half* __restrict__ resf)
{
    const int h0 = blockIdx.x * 4;
    const int o0 = blockIdx.y * 16;
    const int bp = blockIdx.z;
    const int b = bp >> 3, head = bp & 7;

    const __half* qbase = g_qkv + ((size_t)b * 3 * CC + head * HD) * NPIX;
    const __half* vbase = g_qkv + ((size_t)b * 3 * CC + 2 * CC + head * HD) * NPIX;

    __shared__ float lam_s[32][17];
    __shared__ float rel_s[16][25];
    __shared__ float v_s[16][8][68];

    const int tid = threadIdx.x;
    const float scale = 0.1767766953f;

    for (int idx = tid; idx < 32 * 16; idx += 256) {
        int i = idx >> 4, oo = idx & 15;
        lam_s[i][oo] = lam[(size_t)bp * 1024 + i * 32 + o0 + oo] * scale;
    }
    for (int idx = tid; idx < 16 * 25; idx += 256)
        rel_s[idx / 25][idx % 25] = rel[(o0 + idx / 25) * 25 + idx % 25];
    for (int idx = tid; idx < 16 * 8 * 68; idx += 256) {
        int o = idx / 544;
        int rem = idx % 544;
        int rr = rem / 68, c = rem % 68;
        int h = h0 - 2 + rr, w = c - 2;
        float val = 0.f;
        if (h >= 0 && h < HH && w >= 0 && w < WW)
            val = __half2float(vbase[(size_t)(o0 + o) * NPIX + h * WW + w]);
        v_s[o][rr][c] = val;
    }
    __syncthreads();

    const int wr = tid >> 6;
    const int w = tid & 63;
    const int n = (h0 + wr) * WW + w;

    float qreg[32];
    #pragma unroll
    for (int i = 0; i < 32; i++) qreg[i] = __half2float(qbase[(size_t)i * NPIX + n]);

    const size_t obase = ((size_t)b * CC + head * HD + o0) * NPIX + n;

    #pragma unroll 2
    for (int oo = 0; oo < 16; oo++) {
        float content = 0.f;
        #pragma unroll
        for (int i = 0; i < 32; i++) content += qreg[i] * lam_s[i][oo];
        float pos = 0.f;
        #pragma unroll
        for (int dh = 0; dh < 5; dh++)
            #pragma unroll
            for (int dw = 0; dw < 5; dw++)
                pos += rel_s[oo][dh * 5 + dw] * v_s[oo][wr + dh][w + dw];
        float val = content + qreg[o0 + oo] * pos;
        resf[obase + (size_t)oo * NPIX] = __float2half_rn(val);
    }
}

// ---------------------------------------------------------------------------
extern "C" void kernel_launch(void* const* d_in, const int* in_sizes, int n_in,
                              void* d_out, int out_size)
{
    const float* src   = (const float*)d_in[0];
    const float* rel   = (const float*)d_in[1];
    const float* qkv_w = (const float*)d_in[2];
    const float* cpe_w = (const float*)d_in[3];
    const float* cpe_b = (const float*)d_in[4];
    const float* out_w = (const float*)d_in[5];
    const float* out_b = (const float*)d_in[6];
    float* out = (float*)d_out;

    float *pstats, *plam, *ppart;
    __half *pqkv, *psrcf, *presf;
    __half *pwch, *pwcl, *pwqh, *pwql, *pwoh, *pwol;
    cudaGetSymbolAddress((void**)&pqkv,  g_qkv);
    cudaGetSymbolAddress((void**)&pstats,g_stats);
    cudaGetSymbolAddress((void**)&plam,  g_lambda);
    cudaGetSymbolAddress((void**)&ppart, g_lampart);
    cudaGetSymbolAddress((void**)&psrcf, g_srcf);
    cudaGetSymbolAddress((void**)&presf, g_resf);
    cudaGetSymbolAddress((void**)&pwch,  g_wch);
    cudaGetSymbolAddress((void**)&pwcl,  g_wcl);
    cudaGetSymbolAddress((void**)&pwqh,  g_wqh);
    cudaGetSymbolAddress((void**)&pwql,  g_wql);
    cudaGetSymbolAddress((void**)&pwoh,  g_woh);
    cudaGetSymbolAddress((void**)&pwol,  g_wol);

    cudaFuncSetAttribute(gemm_mma, cudaFuncAttributeMaxDynamicSharedMemorySize, SMEM_BYTES);

    // 0) operand prep
    round_pass<<<16384, 256>>>(src, psrcf, BB * CC * NPIX / 4);
    wtc_kernel<<<256, 256>>>(cpe_w, pwch, pwcl);
    split_pass<<<192, 256>>>(qkv_w, pwqh, pwql, 3 * CC * CC / 4);
    split_pass<<<64, 256>>>(out_w, pwoh, pwol, CC * CC / 4);

    // 1) CPE conv (implicit GEMM K=2304, 36 slabs) + bias + residual -> x (fp16)
    gemm_mma<<<dim3(32, 2, 16), 256, SMEM_BYTES>>>(pwch, pwcl, psrcf, 36, CC, 2304, 1,
                                                   nullptr, presf, cpe_b, src);
    // 2) qkv = qkv_w @ x -> fp16
    gemm_mma<<<dim3(32, 6, 16), 256, SMEM_BYTES>>>(pwqh, pwql, presf, 4, 3 * CC, CC, 0,
                                                   nullptr, pqkv, nullptr, nullptr);
    // 3) softmax stats
    softmax_stats_kernel<<<4096, 256>>>(pstats);
    // 4) content lambda
    lambda_partial_kernel<<<dim3(8, 128), 256>>>(pstats, ppart);
    lambda_reduce_kernel<<<128, 256>>>(ppart, plam);
    // 5) fused content + pos-lambda -> result (fp16, overwrites x which is dead)
    fused_kernel<<<dim3(16, 2, 128), 256>>>(plam, rel, presf);
    // 6) output projection -> d_out fp32
    gemm_mma<<<dim3(32, 2, 16), 256, SMEM_BYTES>>>(pwoh, pwol, presf, 4, CC, CC, 0,
                                                   out, nullptr, out_b, nullptr);
}